// round 13
// baseline (speedup 1.0000x reference)
#include <cuda_runtime.h>
#include <cuda_fp16.h>
#include <math_constants.h>
#include <cstdint>

// Problem constants (DistanceNetwork_17514876634042)
#define BB     8
#define SS     4096
#define QQ     4096
#define DD     64
#define BSHOT  2048
#define NTOP   5
#define OUTC   (NTOP + (SS - BSHOT))   // 2053

#define TM       128                 // q rows per CTA
#define TN       64                  // s cols per chunk
#define NCHUNK   (SS / TN)           // 64
#define TOPCHUNK (BSHOT / TN)        // 32
#define WSTAGES  3                   // per-warp smem stages

#define APACK_U4 (8 * 4 * 32)        // A fill region: 1024 uint4 = 16 KB
#define BPACK_U4 (4 * 4 * 32)        // B chunk: 512 uint4 (8192 B)
#define WSLICE_U4 256                // per-warp B slice per chunk: 4 KB
#define CHUNK_BYTES 8192             // BPACK_U4 * 16

// Pre-packed fp16 support fragments (mag folded): [b][chunk][BPACK_U4]
__device__ uint4 g_pack[(size_t)BB * NCHUNK * BPACK_U4];   // 4 MB, L2-resident

// ---------------------------------------------------------------------------
__device__ __forceinline__ unsigned h2(float lo, float hi) {
    __half2 h = __floats2half2_rn(lo, hi);
    return *(unsigned*)&h;
}

// Pre-kernel: one thread per support row. rsqrt-magnitude folded, fp16,
// scattered into the m16n8k16 B-fragment layout.
__global__ void pack_kernel(const float* __restrict__ supp) {
    const int i = blockIdx.x * blockDim.x + threadIdx.x;
    if (i >= BB * SS) return;
    const int b    = i / SS;
    const int s    = i % SS;
    const int ch   = s / TN;
    const int srow = s % TN;

    const float* p = supp + (size_t)i * DD;
    float v[DD];
    float sum = 0.f;
#pragma unroll
    for (int k = 0; k < DD; k += 4) {
        float4 x = *(const float4*)(p + k);
        v[k] = x.x; v[k + 1] = x.y; v[k + 2] = x.z; v[k + 3] = x.w;
        sum += x.x * x.x + x.y * x.y + x.z * x.z + x.w * x.w;
    }
    const float mag = rsqrtf(fmaxf(sum, 1e-10f));
#pragma unroll
    for (int k = 0; k < DD; k++) v[k] *= mag;

    const int bnt  = srow >> 3;        // n8 tile 0..7
    const int bg   = bnt >> 1;         // uint4 group 0..3
    const int bsub = bnt & 1;
    const int blb  = (srow & 7) * 4;   // lane base

    uint2* dst = (uint2*)(g_pack + ((size_t)b * NCHUNK + ch) * BPACK_U4);
#pragma unroll
    for (int ks = 0; ks < 4; ks++) {
        const int k0 = ks * 16;
#pragma unroll
        for (int q = 0; q < 4; q++) {
            unsigned b0 = h2(v[k0 + 2 * q],     v[k0 + 2 * q + 1]);
            unsigned b1 = h2(v[k0 + 8 + 2 * q], v[k0 + 9 + 2 * q]);
            dst[((bg * 4 + ks) * 32 + blb + q) * 2 + bsub] = make_uint2(b0, b1);
        }
    }
}

// ---------------------------------------------------------------------------
__device__ __forceinline__ void mma_f16(float* c, const uint4& a,
                                        unsigned b0, unsigned b1) {
    asm volatile(
        "mma.sync.aligned.m16n8k16.row.col.f32.f16.f16.f32 "
        "{%0,%1,%2,%3}, {%4,%5,%6,%7}, {%8,%9}, {%0,%1,%2,%3};"
        : "+f"(c[0]), "+f"(c[1]), "+f"(c[2]), "+f"(c[3])
        : "r"(a.x), "r"(a.y), "r"(a.z), "r"(a.w), "r"(b0), "r"(b1));
}

__device__ __forceinline__ unsigned smem_u32(const void* p) {
    unsigned a;
    asm("{ .reg .u64 t; cvta.to.shared.u64 t, %1; cvt.u32.u64 %0, t; }" : "=r"(a) : "l"(p));
    return a;
}
__device__ __forceinline__ void cp_async16(unsigned dst, const void* src) {
    asm volatile("cp.async.cg.shared.global [%0], [%1], 16;" :: "r"(dst), "l"(src));
}
#define CP_COMMIT() asm volatile("cp.async.commit_group;" ::: "memory")
#define CP_WAIT1()  asm volatile("cp.async.wait_group 1;" ::: "memory")

__device__ __forceinline__ void stcs(float* p, float v) {
    asm volatile("st.global.cs.f32 [%0], %1;" :: "l"(p), "f"(v) : "memory");
}

__device__ __forceinline__ void ins5(float* t, float v) {
    if (v > t[4]) {
        t[4] = v;
        if (t[4] > t[3]) { float x = t[3]; t[3] = t[4]; t[4] = x;
            if (t[3] > t[2]) { x = t[2]; t[2] = t[3]; t[3] = x;
                if (t[2] > t[1]) { x = t[1]; t[1] = t[2]; t[2] = x;
                    if (t[1] > t[0]) { x = t[0]; t[0] = t[1]; t[1] = x; } } } }
    }
}

// ---------------------------------------------------------------------------
// Fused fp16-MMA cosine GEMM. Barrier-free mainloop; per-warp private
// cp.async 3-stage rings. Pair-walk: (top pp, tail 32+pp), epilogues inlined.
// Grid (QQ/TM, BB) = 256 CTAs, 256 threads, 2 CTAs/SM.
// ---------------------------------------------------------------------------
extern __shared__ uint4 smem4[];

__global__ __launch_bounds__(256, 2)
void fused_kernel(const float* __restrict__ query,
                  float* __restrict__ out) {
    uint4* Apack = smem4;               // aliases stage area (pre-loop only)
    float* red   = (float*)smem4;       // aliases stage area (post-loop only)

    const int b    = blockIdx.y;
    const int q0   = blockIdx.x * TM;
    const int tid  = threadIdx.x;
    const int wid  = tid >> 5;
    const int lane = tid & 31;
    const int wm   = wid & 3;
    const int wn   = wid >> 2;
    const int qd   = lane >> 2;    // 0..7
    const int kq   = lane & 3;     // 0..3

    const float* qb = query + (size_t)b * QQ * DD;

    // ---- fill A (query tile) into fragment layout, fp16 (aliases stages) ----
    {
#pragma unroll
        for (int i = 0; i < 4; i++) {
            const int j  = wid * 4 + i;
            const int ks = j >> 3;
            const int mt = j & 7;
            const int r  = mt * 16 + qd;
            const int k  = ks * 16 + 2 * kq;
            const float* base = qb + (size_t)(q0 + r) * DD + k;
            float2 v00 = *(const float2*)(base);
            float2 v10 = *(const float2*)(base + 8 * DD);
            float2 v01 = *(const float2*)(base + 8);
            float2 v11 = *(const float2*)(base + 8 * DD + 8);
            uint4 u;
            u.x = h2(v00.x, v00.y);
            u.y = h2(v10.x, v10.y);
            u.z = h2(v01.x, v01.y);
            u.w = h2(v11.x, v11.y);
            Apack[(mt * 4 + ks) * 32 + lane] = u;
        }
    }
    __syncthreads();

    // ---- hoist A fragments into registers ----
    uint4 afrag[2][4];
#pragma unroll
    for (int mi = 0; mi < 2; mi++)
#pragma unroll
        for (int ks = 0; ks < 4; ks++)
            afrag[mi][ks] = Apack[((wm * 2 + mi) * 4 + ks) * 32 + lane];
    __syncthreads();   // hoists done before cp.async overwrites the region

    // ---- per-warp private B pipeline (running byte pointers) ----
    const char* srcTop = (const char*)(g_pack + (size_t)b * NCHUNK * BPACK_U4
                                       + wn * WSLICE_U4) + lane * 16;
    const char* srcTail = srcTop + (size_t)TOPCHUNK * CHUNK_BYTES;
    const unsigned wbase = smem_u32(smem4) + (unsigned)(wid * WSTAGES) * 4096u
                         + (unsigned)lane * 16u;
    const uint4* wstage = smem4 + wid * WSTAGES * WSLICE_U4 + lane;

    // prologue: iteration 0 (top chunk 0) -> stage 0; iteration 1 (tail 32) -> stage 1
#pragma unroll
    for (int j = 0; j < 8; j++) cp_async16(wbase + j * 512u, srcTop + j * 512);
    CP_COMMIT();
#pragma unroll
    for (int j = 0; j < 8; j++) cp_async16(wbase + 4096u + j * 512u, srcTail + j * 512);
    CP_COMMIT();

    // Hoisted tail-store row pointers
    const size_t orow0 = (size_t)(b * QQ + q0);
    float* optr[2][2];
#pragma unroll
    for (int mi = 0; mi < 2; mi++) {
        const int r = wm * 32 + mi * 16 + qd;
        optr[mi][0] = out + (orow0 + r) * OUTC + NTOP + wn * 32 + 2 * kq;
        optr[mi][1] = optr[mi][0] + 8 * OUTC;
    }

    float tops[4][5];
#pragma unroll
    for (int s = 0; s < 4; s++)
#pragma unroll
        for (int i = 0; i < 5; i++) tops[s][i] = -CUDART_INF_F;

    int st = 0, stp = 2;     // current stage / prefetch-target stage
    int choff = 0;           // tail-store column offset

    for (int pp = 0; pp < TOPCHUNK; ++pp) {
        const bool pf = (pp < TOPCHUNK - 1);

        // ================= TOP half (chunk pp) =================
        CP_WAIT1();
        if (pf) {
            const unsigned dst = wbase + (unsigned)stp * 4096u;
            const char* src = srcTop + CHUNK_BYTES;
#pragma unroll
            for (int j = 0; j < 8; j++) cp_async16(dst + j * 512u, src + j * 512);
        }
        CP_COMMIT();

        {
            const uint4* Bp = wstage + st * WSLICE_U4;
            float c[2][4][4];
#pragma unroll
            for (int mi = 0; mi < 2; mi++)
#pragma unroll
                for (int ni = 0; ni < 4; ni++)
#pragma unroll
                    for (int j = 0; j < 4; j++) c[mi][ni][j] = 0.f;
#pragma unroll
            for (int ks = 0; ks < 4; ks++) {
                const uint4 B0 = Bp[(ks)     * 32];
                const uint4 B1 = Bp[(4 + ks) * 32];
                mma_f16(c[0][0], afrag[0][ks], B0.x, B0.y);
                mma_f16(c[0][1], afrag[0][ks], B0.z, B0.w);
                mma_f16(c[0][2], afrag[0][ks], B1.x, B1.y);
                mma_f16(c[0][3], afrag[0][ks], B1.z, B1.w);
                mma_f16(c[1][0], afrag[1][ks], B0.x, B0.y);
                mma_f16(c[1][1], afrag[1][ks], B0.z, B0.w);
                mma_f16(c[1][2], afrag[1][ks], B1.x, B1.y);
                mma_f16(c[1][3], afrag[1][ks], B1.z, B1.w);
            }
            // top-5 epilogue (prefiltered)
#pragma unroll
            for (int mi = 0; mi < 2; mi++) {
                float m0 = fmaxf(fmaxf(fmaxf(c[mi][0][0], c[mi][0][1]),
                                        fmaxf(c[mi][1][0], c[mi][1][1])),
                                 fmaxf(fmaxf(c[mi][2][0], c[mi][2][1]),
                                        fmaxf(c[mi][3][0], c[mi][3][1])));
                if (m0 > tops[mi * 2 + 0][4]) {
#pragma unroll
                    for (int ni = 0; ni < 4; ni++) {
                        ins5(tops[mi * 2 + 0], c[mi][ni][0]);
                        ins5(tops[mi * 2 + 0], c[mi][ni][1]);
                    }
                }
                float m1 = fmaxf(fmaxf(fmaxf(c[mi][0][2], c[mi][0][3]),
                                        fmaxf(c[mi][1][2], c[mi][1][3])),
                                 fmaxf(fmaxf(c[mi][2][2], c[mi][2][3]),
                                        fmaxf(c[mi][3][2], c[mi][3][3])));
                if (m1 > tops[mi * 2 + 1][4]) {
#pragma unroll
                    for (int ni = 0; ni < 4; ni++) {
                        ins5(tops[mi * 2 + 1], c[mi][ni][2]);
                        ins5(tops[mi * 2 + 1], c[mi][ni][3]);
                    }
                }
            }
        }
        st  = (st  == WSTAGES - 1) ? 0 : st + 1;
        stp = (stp == WSTAGES - 1) ? 0 : stp + 1;

        // ================= TAIL half (chunk TOPCHUNK+pp) =================
        CP_WAIT1();
        if (pf) {
            const unsigned dst = wbase + (unsigned)stp * 4096u;
            const char* src = srcTail + CHUNK_BYTES;
#pragma unroll
            for (int j = 0; j < 8; j++) cp_async16(dst + j * 512u, src + j * 512);
        }
        CP_COMMIT();

        {
            const uint4* Bp = wstage + st * WSLICE_U4;
            float c[2][4][4];
#pragma unroll
            for (int mi = 0; mi < 2; mi++)
#pragma unroll
                for (int ni = 0; ni < 4; ni++)
#pragma unroll
                    for (int j = 0; j < 4; j++) c[mi][ni][j] = 0.f;
#pragma unroll
            for (int ks = 0; ks < 4; ks++) {
                const uint4 B0 = Bp[(ks)     * 32];
                const uint4 B1 = Bp[(4 + ks) * 32];
                mma_f16(c[0][0], afrag[0][ks], B0.x, B0.y);
                mma_f16(c[0][1], afrag[0][ks], B0.z, B0.w);
                mma_f16(c[0][2], afrag[0][ks], B1.x, B1.y);
                mma_f16(c[0][3], afrag[0][ks], B1.z, B1.w);
                mma_f16(c[1][0], afrag[1][ks], B0.x, B0.y);
                mma_f16(c[1][1], afrag[1][ks], B0.z, B0.w);
                mma_f16(c[1][2], afrag[1][ks], B1.x, B1.y);
                mma_f16(c[1][3], afrag[1][ks], B1.z, B1.w);
            }
            // tail-store epilogue (streaming, scalar: OUTC odd)
#pragma unroll
            for (int mi = 0; mi < 2; mi++) {
                float* p0 = optr[mi][0] + choff;
                float* p1 = optr[mi][1] + choff;
#pragma unroll
                for (int ni = 0; ni < 4; ni++) {
                    const int cc = ni * 8;
                    stcs(p0 + cc,     c[mi][ni][0]);
                    stcs(p0 + cc + 1, c[mi][ni][1]);
                    stcs(p1 + cc,     c[mi][ni][2]);
                    stcs(p1 + cc + 1, c[mi][ni][3]);
                }
            }
        }
        st  = (st  == WSTAGES - 1) ? 0 : st + 1;
        stp = (stp == WSTAGES - 1) ? 0 : stp + 1;

        srcTop  += CHUNK_BYTES;
        srcTail += CHUNK_BYTES;
        choff   += TN;
    }

    // ---- top-5 cross-thread merge (red aliases stage area, dead now) ----
    __syncthreads();
    {
#pragma unroll
        for (int s = 0; s < 4; s++) {
            const int mi = s >> 1, h = s & 1;
            const int row = wm * 32 + mi * 16 + h * 8 + qd;
            float* dst = red + (row * 8 + wn * 4 + kq) * 5;
#pragma unroll
            for (int i = 0; i < 5; i++) dst[i] = tops[s][i];
        }
    }
    __syncthreads();
    if (tid < TM) {
        float t5[5];
#pragma unroll
        for (int i = 0; i < 5; i++) t5[i] = -CUDART_INF_F;
        const float* s = red + tid * 40;
#pragma unroll
        for (int j = 0; j < 40; j++) ins5(t5, s[j]);
        float* orow = out + (size_t)(b * QQ + q0 + tid) * OUTC;
#pragma unroll
        for (int i = 0; i < 5; i++) orow[i] = t5[i];
    }
}

// ---------------------------------------------------------------------------
extern "C" void kernel_launch(void* const* d_in, const int* in_sizes, int n_in,
                              void* d_out, int out_size) {
    const float* supp  = (const float*)d_in[0];
    const float* query = (const float*)d_in[1];
    float* out = (float*)d_out;

    const int smem_bytes = 8 * WSTAGES * 4096;   // 98304 (96 KB)
    cudaFuncSetAttribute(fused_kernel,
                         cudaFuncAttributeMaxDynamicSharedMemorySize, smem_bytes);

    pack_kernel<<<(BB * SS + 127) / 128, 128>>>(supp);

    dim3 grid(QQ / TM, BB);
    fused_kernel<<<grid, 256, smem_bytes>>>(query, out);
}

// round 15
// speedup vs baseline: 1.2366x; 1.2366x over previous
#include <cuda_runtime.h>
#include <cuda_fp16.h>
#include <math_constants.h>
#include <cstdint>

// Problem constants (DistanceNetwork_17514876634042)
#define BB     8
#define SS     4096
#define QQ     4096
#define DD     64
#define BSHOT  2048
#define NTOP   5
#define OUTC   (NTOP + (SS - BSHOT))   // 2053

#define TM       128                 // q rows per CTA
#define TN       64                  // s cols per chunk
#define NCHUNK   (SS / TN)           // 64
#define TOPCHUNK (BSHOT / TN)        // 32
#define WSTAGES  3                   // per-warp smem stages

#define APACK_U4 (8 * 4 * 32)        // A fill region: 1024 uint4 = 16 KB
#define BPACK_U4 (4 * 4 * 32)        // B chunk: 512 uint4 (64 cols)
#define WSLICE_U4 256                // per-warp B slice per chunk: 4 KB

// Interleave top-5 chunks and tail-store chunks: top0,tail0,top1,tail1,...
#define CHUNK_OF(i) (((i) & 1) ? (TOPCHUNK + ((i) >> 1)) : ((i) >> 1))

// Pre-packed fp16 support fragments (mag folded): [b][chunk][BPACK_U4]
__device__ uint4 g_pack[(size_t)BB * NCHUNK * BPACK_U4];   // 4 MB, L2-resident

// ---------------------------------------------------------------------------
__device__ __forceinline__ unsigned h2(float lo, float hi) {
    __half2 h = __floats2half2_rn(lo, hi);
    return *(unsigned*)&h;
}

// Pre-kernel: one thread per support row. rsqrt-magnitude folded, fp16,
// scattered into the m16n8k16 B-fragment layout.
__global__ void pack_kernel(const float* __restrict__ supp) {
    const int i = blockIdx.x * blockDim.x + threadIdx.x;
    if (i >= BB * SS) return;
    const int b    = i / SS;
    const int s    = i % SS;
    const int ch   = s / TN;
    const int srow = s % TN;

    const float* p = supp + (size_t)i * DD;
    float v[DD];
    float sum = 0.f;
#pragma unroll
    for (int k = 0; k < DD; k += 4) {
        float4 x = *(const float4*)(p + k);
        v[k] = x.x; v[k + 1] = x.y; v[k + 2] = x.z; v[k + 3] = x.w;
        sum += x.x * x.x + x.y * x.y + x.z * x.z + x.w * x.w;
    }
    const float mag = rsqrtf(fmaxf(sum, 1e-10f));
#pragma unroll
    for (int k = 0; k < DD; k++) v[k] *= mag;

    const int bnt  = srow >> 3;        // n8 tile 0..7
    const int bg   = bnt >> 1;         // uint4 group 0..3
    const int bsub = bnt & 1;
    const int blb  = (srow & 7) * 4;   // lane base

    uint2* dst = (uint2*)(g_pack + ((size_t)b * NCHUNK + ch) * BPACK_U4);
#pragma unroll
    for (int ks = 0; ks < 4; ks++) {
        const int k0 = ks * 16;
#pragma unroll
        for (int q = 0; q < 4; q++) {
            unsigned b0 = h2(v[k0 + 2 * q],     v[k0 + 2 * q + 1]);
            unsigned b1 = h2(v[k0 + 8 + 2 * q], v[k0 + 9 + 2 * q]);
            dst[((bg * 4 + ks) * 32 + blb + q) * 2 + bsub] = make_uint2(b0, b1);
        }
    }
}

// ---------------------------------------------------------------------------
__device__ __forceinline__ void mma_f16(float* c, const uint4& a,
                                        unsigned b0, unsigned b1) {
    asm volatile(
        "mma.sync.aligned.m16n8k16.row.col.f32.f16.f16.f32 "
        "{%0,%1,%2,%3}, {%4,%5,%6,%7}, {%8,%9}, {%0,%1,%2,%3};"
        : "+f"(c[0]), "+f"(c[1]), "+f"(c[2]), "+f"(c[3])
        : "r"(a.x), "r"(a.y), "r"(a.z), "r"(a.w), "r"(b0), "r"(b1));
}

__device__ __forceinline__ unsigned smem_u32(const void* p) {
    unsigned a;
    asm("{ .reg .u64 t; cvta.to.shared.u64 t, %1; cvt.u32.u64 %0, t; }" : "=r"(a) : "l"(p));
    return a;
}
__device__ __forceinline__ void cp_async16(unsigned dst, const void* src) {
    asm volatile("cp.async.cg.shared.global [%0], [%1], 16;" :: "r"(dst), "l"(src));
}
#define CP_COMMIT() asm volatile("cp.async.commit_group;" ::: "memory")
#define CP_WAIT1()  asm volatile("cp.async.wait_group 1;" ::: "memory")

__device__ __forceinline__ void ins5(float* t, float v) {
    if (v > t[4]) {
        t[4] = v;
        if (t[4] > t[3]) { float x = t[3]; t[3] = t[4]; t[4] = x;
            if (t[3] > t[2]) { x = t[2]; t[2] = t[3]; t[3] = x;
                if (t[2] > t[1]) { x = t[1]; t[1] = t[2]; t[2] = x;
                    if (t[1] > t[0]) { x = t[0]; t[0] = t[1]; t[1] = x; } } } }
    }
}

// ---------------------------------------------------------------------------
// Fused fp16-MMA cosine GEMM. Barrier-free mainloop; per-warp private
// cp.async 3-stage rings. Tail stores staged through the just-consumed
// B stage (in-place swizzled 32x32 tile) for coalesced STG.
// Grid (QQ/TM, BB) = 256 CTAs, 256 threads, 2 CTAs/SM.
// ---------------------------------------------------------------------------
extern __shared__ uint4 smem4[];

__global__ __launch_bounds__(256, 2)
void fused_kernel(const float* __restrict__ query,
                  float* __restrict__ out) {
    uint4* Apack = smem4;               // aliases stage area (pre-loop only)
    float* red   = (float*)smem4;       // aliases stage area (post-loop only)

    const int b    = blockIdx.y;
    const int q0   = blockIdx.x * TM;
    const int tid  = threadIdx.x;
    const int wid  = tid >> 5;
    const int lane = tid & 31;
    const int wm   = wid & 3;
    const int wn   = wid >> 2;
    const int qd   = lane >> 2;    // 0..7
    const int kq   = lane & 3;     // 0..3

    const float* qb = query + (size_t)b * QQ * DD;

    // ---- fill A (query tile) into fragment layout, fp16 (aliases stages) ----
    {
#pragma unroll
        for (int i = 0; i < 4; i++) {
            const int j  = wid * 4 + i;
            const int ks = j >> 3;
            const int mt = j & 7;
            const int r  = mt * 16 + qd;
            const int k  = ks * 16 + 2 * kq;
            const float* base = qb + (size_t)(q0 + r) * DD + k;
            float2 v00 = *(const float2*)(base);
            float2 v10 = *(const float2*)(base + 8 * DD);
            float2 v01 = *(const float2*)(base + 8);
            float2 v11 = *(const float2*)(base + 8 * DD + 8);
            uint4 u;
            u.x = h2(v00.x, v00.y);
            u.y = h2(v10.x, v10.y);
            u.z = h2(v01.x, v01.y);
            u.w = h2(v11.x, v11.y);
            Apack[(mt * 4 + ks) * 32 + lane] = u;
        }
    }
    __syncthreads();

    // ---- hoist A fragments into registers ----
    uint4 afrag[2][4];
#pragma unroll
    for (int mi = 0; mi < 2; mi++)
#pragma unroll
        for (int ks = 0; ks < 4; ks++)
            afrag[mi][ks] = Apack[((wm * 2 + mi) * 4 + ks) * 32 + lane];
    __syncthreads();   // hoists done before cp.async overwrites the region

    // ---- per-warp private B pipeline ----
    const uint4* gslice = g_pack + (size_t)b * NCHUNK * BPACK_U4 + wn * WSLICE_U4 + lane;
    const unsigned wbase = smem_u32(smem4) + (unsigned)(wid * WSTAGES) * 4096u
                         + (unsigned)lane * 16u;
    const uint4* wstage = smem4 + wid * WSTAGES * WSLICE_U4 + lane;
    float* wtile_base = (float*)(smem4 + wid * WSTAGES * WSLICE_U4);  // +st*1024 floats

    // prologue: iterations 0,1 into stages 0,1 (proven j*512 pattern)
#pragma unroll
    for (int pi = 0; pi < 2; pi++) {
        const unsigned dst = wbase + (unsigned)pi * 4096u;
        const uint4* src = gslice + (size_t)CHUNK_OF(pi) * BPACK_U4;
#pragma unroll
        for (int j = 0; j < 8; j++)
            cp_async16(dst + j * 512u, src + j * 32);
        CP_COMMIT();
    }

    // Coalesced tail-store base: row wm*32+T, col NTOP + wn*32 + lane (+choff)
    float* obase = out + ((size_t)(b * QQ + q0 + wm * 32)) * OUTC + NTOP + wn * 32 + lane;

    float tops[4][5];
#pragma unroll
    for (int s = 0; s < 4; s++)
#pragma unroll
        for (int i = 0; i < 5; i++) tops[s][i] = -CUDART_INF_F;

    int st = 0, stp = 2;           // current stage / prefetch-target stage
    for (int it = 0; it < NCHUNK; ++it) {
        const int ch = CHUNK_OF(it);

        CP_WAIT1();   // group for iteration it complete (warp-private)

        // ---- prefetch iteration it+2 into stage stp ----
        if (it + 2 < NCHUNK) {
            const unsigned dst = wbase + (unsigned)stp * 4096u;
            const uint4* src = gslice + (size_t)CHUNK_OF(it + 2) * BPACK_U4;
#pragma unroll
            for (int j = 0; j < 8; j++)
                cp_async16(dst + j * 512u, src + j * 32);
        }
        CP_COMMIT();

        // ---- MMA over K=64 (4 k16-steps) from private stage ----
        const uint4* Bp = wstage + st * WSLICE_U4;
        float c[2][4][4];
#pragma unroll
        for (int mi = 0; mi < 2; mi++)
#pragma unroll
            for (int ni = 0; ni < 4; ni++)
#pragma unroll
                for (int j = 0; j < 4; j++) c[mi][ni][j] = 0.f;

#pragma unroll
        for (int ks = 0; ks < 4; ks++) {
            const uint4 B0 = Bp[(ks)     * 32];
            const uint4 B1 = Bp[(4 + ks) * 32];
            mma_f16(c[0][0], afrag[0][ks], B0.x, B0.y);
            mma_f16(c[0][1], afrag[0][ks], B0.z, B0.w);
            mma_f16(c[0][2], afrag[0][ks], B1.x, B1.y);
            mma_f16(c[0][3], afrag[0][ks], B1.z, B1.w);
            mma_f16(c[1][0], afrag[1][ks], B0.x, B0.y);
            mma_f16(c[1][1], afrag[1][ks], B0.z, B0.w);
            mma_f16(c[1][2], afrag[1][ks], B1.x, B1.y);
            mma_f16(c[1][3], afrag[1][ks], B1.z, B1.w);
        }

        // ---- epilogue ----
        if (ch < TOPCHUNK) {
            // prefilter: slot-max tree first; serial chain only when it matters
#pragma unroll
            for (int mi = 0; mi < 2; mi++) {
                float m0 = fmaxf(fmaxf(fmaxf(c[mi][0][0], c[mi][0][1]),
                                        fmaxf(c[mi][1][0], c[mi][1][1])),
                                 fmaxf(fmaxf(c[mi][2][0], c[mi][2][1]),
                                        fmaxf(c[mi][3][0], c[mi][3][1])));
                if (m0 > tops[mi * 2 + 0][4]) {
#pragma unroll
                    for (int ni = 0; ni < 4; ni++) {
                        ins5(tops[mi * 2 + 0], c[mi][ni][0]);
                        ins5(tops[mi * 2 + 0], c[mi][ni][1]);
                    }
                }
                float m1 = fmaxf(fmaxf(fmaxf(c[mi][0][2], c[mi][0][3]),
                                        fmaxf(c[mi][1][2], c[mi][1][3])),
                                 fmaxf(fmaxf(c[mi][2][2], c[mi][2][3]),
                                        fmaxf(c[mi][3][2], c[mi][3][3])));
                if (m1 > tops[mi * 2 + 1][4]) {
#pragma unroll
                    for (int ni = 0; ni < 4; ni++) {
                        ins5(tops[mi * 2 + 1], c[mi][ni][2]);
                        ins5(tops[mi * 2 + 1], c[mi][ni][3]);
                    }
                }
            }
        } else {
            // Stage into the just-consumed B stage as a swizzled 32x32 tile,
            // then store coalesced (consecutive lanes -> consecutive cols).
            float* tile = wtile_base + st * 1024;   // 4KB = 32*32 floats
            const int swz = qd << 2;                // (row&7)*4; rows share qd
#pragma unroll
            for (int mi = 0; mi < 2; mi++) {
                const int T0 = mi * 16 + qd;
#pragma unroll
                for (int ni = 0; ni < 4; ni++) {
                    const int col = ni * 8 + 2 * kq;        // even; swz bits >= 2
                    *(float2*)&tile[T0 * 32 + (col ^ swz)] =
                        make_float2(c[mi][ni][0], c[mi][ni][1]);
                    *(float2*)&tile[(T0 + 8) * 32 + (col ^ swz)] =
                        make_float2(c[mi][ni][2], c[mi][ni][3]);
                }
            }
            __syncwarp();
            float* op = obase + (size_t)(ch - TOPCHUNK) * TN;
#pragma unroll
            for (int T = 0; T < 32; T++) {
                float v = tile[T * 32 + (lane ^ ((T & 7) << 2))];
                op[(size_t)T * OUTC] = v;           // scalar: OUTC odd
            }
            __syncwarp();   // all reads done before next DMA reuses this stage
        }

        st  = (st  == WSTAGES - 1) ? 0 : st + 1;
        stp = (stp == WSTAGES - 1) ? 0 : stp + 1;
    }

    // ---- top-5 cross-thread merge (red aliases stage area, dead now) ----
    __syncthreads();
    {
#pragma unroll
        for (int s = 0; s < 4; s++) {
            const int mi = s >> 1, h = s & 1;
            const int row = wm * 32 + mi * 16 + h * 8 + qd;
            float* dst = red + (row * 8 + wn * 4 + kq) * 5;
#pragma unroll
            for (int i = 0; i < 5; i++) dst[i] = tops[s][i];
        }
    }
    __syncthreads();
    if (tid < TM) {
        float t5[5];
#pragma unroll
        for (int i = 0; i < 5; i++) t5[i] = -CUDART_INF_F;
        const float* s = red + tid * 40;
#pragma unroll
        for (int j = 0; j < 40; j++) ins5(t5, s[j]);
        float* orow = out + (size_t)(b * QQ + q0 + tid) * OUTC;
#pragma unroll
        for (int i = 0; i < 5; i++) orow[i] = t5[i];
    }
}

// ---------------------------------------------------------------------------
extern "C" void kernel_launch(void* const* d_in, const int* in_sizes, int n_in,
                              void* d_out, int out_size) {
    const float* supp  = (const float*)d_in[0];
    const float* query = (const float*)d_in[1];
    float* out = (float*)d_out;

    const int smem_bytes = 8 * WSTAGES * 4096;   // 98304 (96 KB)
    cudaFuncSetAttribute(fused_kernel,
                         cudaFuncAttributeMaxDynamicSharedMemorySize, smem_bytes);

    pack_kernel<<<(BB * SS + 127) / 128, 128>>>(supp);

    dim3 grid(QQ / TM, BB);
    fused_kernel<<<grid, 256, smem_bytes>>>(query, out);
}

// round 16
// speedup vs baseline: 1.2369x; 1.0002x over previous
#include <cuda_runtime.h>
#include <cuda_fp16.h>
#include <math_constants.h>
#include <cstdint>

// Problem constants (DistanceNetwork_17514876634042)
#define BB     8
#define SS     4096
#define QQ     4096
#define DD     64
#define BSHOT  2048
#define NTOP   5
#define OUTC   (NTOP + (SS - BSHOT))   // 2053

#define TM       128                 // q rows per CTA
#define TN       64                  // s cols per chunk
#define NCHUNK   (SS / TN)           // 64
#define TOPCHUNK (BSHOT / TN)        // 32
#define WSTAGES  3                   // per-warp smem stages

#define APACK_U4 (8 * 4 * 32)        // A fill region: 1024 uint4 = 16 KB
#define BPACK_U4 (4 * 4 * 32)        // B chunk: 512 uint4 (64 cols)
#define WSLICE_U4 256                // per-warp B slice per chunk: 4 KB

// Interleave top-5 chunks and tail-store chunks: top0,tail0,top1,tail1,...
#define CHUNK_OF(i) (((i) & 1) ? (TOPCHUNK + ((i) >> 1)) : ((i) >> 1))

// Pre-packed fp16 support fragments (mag folded): [b][chunk][BPACK_U4]
__device__ uint4 g_pack[(size_t)BB * NCHUNK * BPACK_U4];   // 4 MB, L2-resident

// ---------------------------------------------------------------------------
__device__ __forceinline__ unsigned h2(float lo, float hi) {
    __half2 h = __floats2half2_rn(lo, hi);
    return *(unsigned*)&h;
}

// Pre-kernel: one thread per support row. rsqrt-magnitude folded, fp16,
// scattered into the m16n8k16 B-fragment layout.
__global__ void pack_kernel(const float* __restrict__ supp) {
    const int i = blockIdx.x * blockDim.x + threadIdx.x;
    if (i >= BB * SS) return;
    const int b    = i / SS;
    const int s    = i % SS;
    const int ch   = s / TN;
    const int srow = s % TN;

    const float* p = supp + (size_t)i * DD;
    float v[DD];
    float sum = 0.f;
#pragma unroll
    for (int k = 0; k < DD; k += 4) {
        float4 x = *(const float4*)(p + k);
        v[k] = x.x; v[k + 1] = x.y; v[k + 2] = x.z; v[k + 3] = x.w;
        sum += x.x * x.x + x.y * x.y + x.z * x.z + x.w * x.w;
    }
    const float mag = rsqrtf(fmaxf(sum, 1e-10f));
#pragma unroll
    for (int k = 0; k < DD; k++) v[k] *= mag;

    const int bnt  = srow >> 3;        // n8 tile 0..7
    const int bg   = bnt >> 1;         // uint4 group 0..3
    const int bsub = bnt & 1;
    const int blb  = (srow & 7) * 4;   // lane base

    uint2* dst = (uint2*)(g_pack + ((size_t)b * NCHUNK + ch) * BPACK_U4);
#pragma unroll
    for (int ks = 0; ks < 4; ks++) {
        const int k0 = ks * 16;
#pragma unroll
        for (int q = 0; q < 4; q++) {
            unsigned b0 = h2(v[k0 + 2 * q],     v[k0 + 2 * q + 1]);
            unsigned b1 = h2(v[k0 + 8 + 2 * q], v[k0 + 9 + 2 * q]);
            dst[((bg * 4 + ks) * 32 + blb + q) * 2 + bsub] = make_uint2(b0, b1);
        }
    }
}

// ---------------------------------------------------------------------------
__device__ __forceinline__ void mma_f16(float* c, const uint4& a,
                                        unsigned b0, unsigned b1) {
    asm volatile(
        "mma.sync.aligned.m16n8k16.row.col.f32.f16.f16.f32 "
        "{%0,%1,%2,%3}, {%4,%5,%6,%7}, {%8,%9}, {%0,%1,%2,%3};"
        : "+f"(c[0]), "+f"(c[1]), "+f"(c[2]), "+f"(c[3])
        : "r"(a.x), "r"(a.y), "r"(a.z), "r"(a.w), "r"(b0), "r"(b1));
}

__device__ __forceinline__ unsigned smem_u32(const void* p) {
    unsigned a;
    asm("{ .reg .u64 t; cvta.to.shared.u64 t, %1; cvt.u32.u64 %0, t; }" : "=r"(a) : "l"(p));
    return a;
}
__device__ __forceinline__ void cp_async16(unsigned dst, const void* src) {
    asm volatile("cp.async.cg.shared.global [%0], [%1], 16;" :: "r"(dst), "l"(src));
}
#define CP_COMMIT() asm volatile("cp.async.commit_group;" ::: "memory")
#define CP_WAIT2()  asm volatile("cp.async.wait_group 2;" ::: "memory")

__device__ __forceinline__ void stcs(float* p, float v) {
    asm volatile("st.global.cs.f32 [%0], %1;" :: "l"(p), "f"(v) : "memory");
}

__device__ __forceinline__ void ins5(float* t, float v) {
    if (v > t[4]) {
        t[4] = v;
        if (t[4] > t[3]) { float x = t[3]; t[3] = t[4]; t[4] = x;
            if (t[3] > t[2]) { x = t[2]; t[2] = t[3]; t[3] = x;
                if (t[2] > t[1]) { x = t[1]; t[1] = t[2]; t[2] = x;
                    if (t[1] > t[0]) { x = t[0]; t[0] = t[1]; t[1] = x; } } } }
    }
}

// ---------------------------------------------------------------------------
// Fused fp16-MMA cosine GEMM. Barrier-free mainloop; per-warp private
// cp.async 3-stage rings (prefetch issued BEFORE the wait; wait_group 2
// gives the same completion guarantee with an earlier DMA start).
// Tail stores staged through the just-consumed B stage for coalesced STG.
// Grid (QQ/TM, BB) = 256 CTAs, 256 threads, 2 CTAs/SM.
// ---------------------------------------------------------------------------
extern __shared__ uint4 smem4[];

__global__ __launch_bounds__(256, 2)
void fused_kernel(const float* __restrict__ query,
                  float* __restrict__ out) {
    uint4* Apack = smem4;               // aliases stage area (pre-loop only)
    float* red   = (float*)smem4;       // aliases stage area (post-loop only)

    const int b    = blockIdx.y;
    const int q0   = blockIdx.x * TM;
    const int tid  = threadIdx.x;
    const int wid  = tid >> 5;
    const int lane = tid & 31;
    const int wm   = wid & 3;
    const int wn   = wid >> 2;
    const int qd   = lane >> 2;    // 0..7
    const int kq   = lane & 3;     // 0..3

    const float* qb = query + (size_t)b * QQ * DD;

    // ---- fill A (query tile) into fragment layout, fp16 (aliases stages) ----
    {
#pragma unroll
        for (int i = 0; i < 4; i++) {
            const int j  = wid * 4 + i;
            const int ks = j >> 3;
            const int mt = j & 7;
            const int r  = mt * 16 + qd;
            const int k  = ks * 16 + 2 * kq;
            const float* base = qb + (size_t)(q0 + r) * DD + k;
            float2 v00 = *(const float2*)(base);
            float2 v10 = *(const float2*)(base + 8 * DD);
            float2 v01 = *(const float2*)(base + 8);
            float2 v11 = *(const float2*)(base + 8 * DD + 8);
            uint4 u;
            u.x = h2(v00.x, v00.y);
            u.y = h2(v10.x, v10.y);
            u.z = h2(v01.x, v01.y);
            u.w = h2(v11.x, v11.y);
            Apack[(mt * 4 + ks) * 32 + lane] = u;
        }
    }
    __syncthreads();

    // ---- hoist A fragments into registers ----
    uint4 afrag[2][4];
#pragma unroll
    for (int mi = 0; mi < 2; mi++)
#pragma unroll
        for (int ks = 0; ks < 4; ks++)
            afrag[mi][ks] = Apack[((wm * 2 + mi) * 4 + ks) * 32 + lane];
    __syncthreads();   // hoists done before cp.async overwrites the region

    // ---- per-warp private B pipeline ----
    const uint4* gslice = g_pack + (size_t)b * NCHUNK * BPACK_U4 + wn * WSLICE_U4 + lane;
    const unsigned wbase = smem_u32(smem4) + (unsigned)(wid * WSTAGES) * 4096u
                         + (unsigned)lane * 16u;
    const uint4* wstage = smem4 + wid * WSTAGES * WSLICE_U4 + lane;
    float* wtile_base = (float*)(smem4 + wid * WSTAGES * WSLICE_U4);  // +st*1024 floats

    // prologue: iterations 0,1 into stages 0,1 (proven j*512 pattern)
#pragma unroll
    for (int pi = 0; pi < 2; pi++) {
        const unsigned dst = wbase + (unsigned)pi * 4096u;
        const uint4* src = gslice + (size_t)CHUNK_OF(pi) * BPACK_U4;
#pragma unroll
        for (int j = 0; j < 8; j++)
            cp_async16(dst + j * 512u, src + j * 32);
        CP_COMMIT();
    }

    // Coalesced tail-store base: row wm*32+T, col NTOP + wn*32 + lane (+choff)
    float* obase = out + ((size_t)(b * QQ + q0 + wm * 32)) * OUTC + NTOP + wn * 32 + lane;

    float tops[4][5];
#pragma unroll
    for (int s = 0; s < 4; s++)
#pragma unroll
        for (int i = 0; i < 5; i++) tops[s][i] = -CUDART_INF_F;

    int st = 0, stp = 2;           // current stage / prefetch-target stage
    for (int it = 0; it < NCHUNK; ++it) {
        const int ch = CHUNK_OF(it);

        // ---- prefetch iteration it+2 into stage stp (BEFORE the wait:
        //      stage stp was last read at iteration it-1, in-order safe;
        //      wait_group 2 below keeps the same completion guarantee) ----
        if (it + 2 < NCHUNK) {
            const unsigned dst = wbase + (unsigned)stp * 4096u;
            const uint4* src = gslice + (size_t)CHUNK_OF(it + 2) * BPACK_U4;
#pragma unroll
            for (int j = 0; j < 8; j++)
                cp_async16(dst + j * 512u, src + j * 32);
        }
        CP_COMMIT();
        CP_WAIT2();   // group carrying iteration it's data is outside last-2

        // ---- MMA over K=64 (4 k16-steps) from private stage ----
        const uint4* Bp = wstage + st * WSLICE_U4;
        float c[2][4][4];
#pragma unroll
        for (int mi = 0; mi < 2; mi++)
#pragma unroll
            for (int ni = 0; ni < 4; ni++)
#pragma unroll
                for (int j = 0; j < 4; j++) c[mi][ni][j] = 0.f;

#pragma unroll
        for (int ks = 0; ks < 4; ks++) {
            const uint4 B0 = Bp[(ks)     * 32];
            const uint4 B1 = Bp[(4 + ks) * 32];
            mma_f16(c[0][0], afrag[0][ks], B0.x, B0.y);
            mma_f16(c[0][1], afrag[0][ks], B0.z, B0.w);
            mma_f16(c[0][2], afrag[0][ks], B1.x, B1.y);
            mma_f16(c[0][3], afrag[0][ks], B1.z, B1.w);
            mma_f16(c[1][0], afrag[1][ks], B0.x, B0.y);
            mma_f16(c[1][1], afrag[1][ks], B0.z, B0.w);
            mma_f16(c[1][2], afrag[1][ks], B1.x, B1.y);
            mma_f16(c[1][3], afrag[1][ks], B1.z, B1.w);
        }

        // ---- epilogue ----
        if (ch < TOPCHUNK) {
            // prefilter: slot-max tree first; serial chain only when it matters
#pragma unroll
            for (int mi = 0; mi < 2; mi++) {
                float m0 = fmaxf(fmaxf(fmaxf(c[mi][0][0], c[mi][0][1]),
                                        fmaxf(c[mi][1][0], c[mi][1][1])),
                                 fmaxf(fmaxf(c[mi][2][0], c[mi][2][1]),
                                        fmaxf(c[mi][3][0], c[mi][3][1])));
                if (m0 > tops[mi * 2 + 0][4]) {
#pragma unroll
                    for (int ni = 0; ni < 4; ni++) {
                        ins5(tops[mi * 2 + 0], c[mi][ni][0]);
                        ins5(tops[mi * 2 + 0], c[mi][ni][1]);
                    }
                }
                float m1 = fmaxf(fmaxf(fmaxf(c[mi][0][2], c[mi][0][3]),
                                        fmaxf(c[mi][1][2], c[mi][1][3])),
                                 fmaxf(fmaxf(c[mi][2][2], c[mi][2][3]),
                                        fmaxf(c[mi][3][2], c[mi][3][3])));
                if (m1 > tops[mi * 2 + 1][4]) {
#pragma unroll
                    for (int ni = 0; ni < 4; ni++) {
                        ins5(tops[mi * 2 + 1], c[mi][ni][2]);
                        ins5(tops[mi * 2 + 1], c[mi][ni][3]);
                    }
                }
            }
        } else {
            // Stage into the just-consumed B stage as a swizzled 32x32 tile,
            // then store coalesced (consecutive lanes -> consecutive cols).
            float* tile = wtile_base + st * 1024;   // 4KB = 32*32 floats
            const int swz = qd << 2;                // (row&7)*4; rows share qd
#pragma unroll
            for (int mi = 0; mi < 2; mi++) {
                const int T0 = mi * 16 + qd;
#pragma unroll
                for (int ni = 0; ni < 4; ni++) {
                    const int col = ni * 8 + 2 * kq;        // even; swz bits >= 2
                    *(float2*)&tile[T0 * 32 + (col ^ swz)] =
                        make_float2(c[mi][ni][0], c[mi][ni][1]);
                    *(float2*)&tile[(T0 + 8) * 32 + (col ^ swz)] =
                        make_float2(c[mi][ni][2], c[mi][ni][3]);
                }
            }
            __syncwarp();
            float* op = obase + (size_t)(ch - TOPCHUNK) * TN;
#pragma unroll
            for (int T = 0; T < 32; T++) {
                float v = tile[T * 32 + (lane ^ ((T & 7) << 2))];
                stcs(op + (size_t)T * OUTC, v);     // scalar: OUTC odd; streaming
            }
            __syncwarp();   // all reads done before next DMA reuses this stage
        }

        st  = (st  == WSTAGES - 1) ? 0 : st + 1;
        stp = (stp == WSTAGES - 1) ? 0 : stp + 1;
    }

    // ---- top-5 cross-thread merge (red aliases stage area, dead now) ----
    __syncthreads();
    {
#pragma unroll
        for (int s = 0; s < 4; s++) {
            const int mi = s >> 1, h = s & 1;
            const int row = wm * 32 + mi * 16 + h * 8 + qd;
            float* dst = red + (row * 8 + wn * 4 + kq) * 5;
#pragma unroll
            for (int i = 0; i < 5; i++) dst[i] = tops[s][i];
        }
    }
    __syncthreads();
    if (tid < TM) {
        float t5[5];
#pragma unroll
        for (int i = 0; i < 5; i++) t5[i] = -CUDART_INF_F;
        const float* s = red + tid * 40;
#pragma unroll
        for (int j = 0; j < 40; j++) ins5(t5, s[j]);
        float* orow = out + (size_t)(b * QQ + q0 + tid) * OUTC;
#pragma unroll
        for (int i = 0; i < 5; i++) orow[i] = t5[i];
    }
}

// ---------------------------------------------------------------------------
extern "C" void kernel_launch(void* const* d_in, const int* in_sizes, int n_in,
                              void* d_out, int out_size) {
    const float* supp  = (const float*)d_in[0];
    const float* query = (const float*)d_in[1];
    float* out = (float*)d_out;

    const int smem_bytes = 8 * WSTAGES * 4096;   // 98304 (96 KB)
    cudaFuncSetAttribute(fused_kernel,
                         cudaFuncAttributeMaxDynamicSharedMemorySize, smem_bytes);

    pack_kernel<<<(BB * SS + 127) / 128, 128>>>(supp);

    dim3 grid(QQ / TM, BB);
    fused_kernel<<<grid, 256, smem_bytes>>>(query, out);
}